// round 7
// baseline (speedup 1.0000x reference)
#include <cuda_runtime.h>
#include <cuda_fp16.h>
#include <math.h>

#define Bn    16
#define Hn    512
#define Wn    512
#define HWn   (Hn * Wn)
#define NPIX  (Bn * HWn)

#define TW    32
#define TH    32
#define EXTH  38
#define HSS   36   // h-sum row stride (floats)

#define RBLK  4096 // residual blocks (1024 px, 256/image)
#define LBLK  4096 // localvar blocks (16 x 16 x 16)

// Scratch (__device__ globals; rewritten every call). +16 pad: phase-A does
// aligned 16-half over-reads near the right edge of the last row.
__device__ __half g_rsrh[NPIX + 16];          // signed fp16: sign bit = gate off
__device__ float  g_psum[RBLK], g_psq[RBLK];  // residual per-block partials
__device__ float  g_pS[LBLK];                 // localvar per-block partials

__device__ __forceinline__ float warpRed(float v) {
    #pragma unroll
    for (int o = 16; o; o >>= 1) v += __shfl_down_sync(0xffffffffu, v, o);
    return v;
}
__device__ __forceinline__ double warpRedD(double v) {
    #pragma unroll
    for (int o = 16; o; o >>= 1) v += __shfl_down_sync(0xffffffffu, v, o);
    return v;
}
__device__ __forceinline__ int refl(int i) {
    i = (i < 0) ? -i : i;
    return (i >= Hn) ? (2 * (Hn - 1) - i) : i;
}

// ---------------------------------------------------------------------------
// Residual: rs = sum_c |gt-out|; gate vs sum_c |gt-ema| in the sign bit of a
// packed fp16 store; fp32 per-block sum/sumsq partials. HBM-roof kernel.
// ---------------------------------------------------------------------------
__global__ __launch_bounds__(256) void k_residual(const float* __restrict__ outp,
                                                  const float* __restrict__ emap,
                                                  const float* __restrict__ gtp) {
    int blk = blockIdx.x;
    int b   = blk >> 8;
    int p   = (blk & 255) * 1024 + threadIdx.x * 4;
    size_t base = (size_t)b * 3 * HWn + p;

    float4 g0 = *(const float4*)(gtp  + base);
    float4 g1 = *(const float4*)(gtp  + base + HWn);
    float4 g2 = *(const float4*)(gtp  + base + 2 * HWn);
    float4 o0 = *(const float4*)(outp + base);
    float4 o1 = *(const float4*)(outp + base + HWn);
    float4 o2 = *(const float4*)(outp + base + 2 * HWn);
    float4 e0 = *(const float4*)(emap + base);
    float4 e1 = *(const float4*)(emap + base + HWn);
    float4 e2 = *(const float4*)(emap + base + 2 * HWn);

    float4 rs, re;
    rs.x = fabsf(g0.x-o0.x)+fabsf(g1.x-o1.x)+fabsf(g2.x-o2.x);
    rs.y = fabsf(g0.y-o0.y)+fabsf(g1.y-o1.y)+fabsf(g2.y-o2.y);
    rs.z = fabsf(g0.z-o0.z)+fabsf(g1.z-o1.z)+fabsf(g2.z-o2.z);
    rs.w = fabsf(g0.w-o0.w)+fabsf(g1.w-o1.w)+fabsf(g2.w-o2.w);
    re.x = fabsf(g0.x-e0.x)+fabsf(g1.x-e1.x)+fabsf(g2.x-e2.x);
    re.y = fabsf(g0.y-e0.y)+fabsf(g1.y-e1.y)+fabsf(g2.y-e2.y);
    re.z = fabsf(g0.z-e0.z)+fabsf(g1.z-e1.z)+fabsf(g2.z-e2.z);
    re.w = fabsf(g0.w-e0.w)+fabsf(g1.w-e1.w)+fabsf(g2.w-e2.w);

    float4 sv;   // sign bit encodes gate (negative => gated off)
    sv.x = (rs.x < re.x) ? -rs.x : rs.x;
    sv.y = (rs.y < re.y) ? -rs.y : rs.y;
    sv.z = (rs.z < re.z) ? -rs.z : rs.z;
    sv.w = (rs.w < re.w) ? -rs.w : rs.w;

    __half2 p0 = __floats2half2_rn(sv.x, sv.y);
    __half2 p1 = __floats2half2_rn(sv.z, sv.w);
    uint2 pk;
    pk.x = *(unsigned int*)&p0;
    pk.y = *(unsigned int*)&p1;
    *(uint2*)(g_rsrh + (size_t)b * HWn + p) = pk;

    float lsum = rs.x + rs.y + rs.z + rs.w;
    float lsq  = rs.x*rs.x + rs.y*rs.y + rs.z*rs.z + rs.w*rs.w;

    lsum = warpRed(lsum); lsq = warpRed(lsq);
    __shared__ float sh_s[8], sh_q[8];
    int lane = threadIdx.x & 31, w = threadIdx.x >> 5;
    if (lane == 0) { sh_s[w] = lsum; sh_q[w] = lsq; }
    __syncthreads();
    if (w == 0) {
        lsum = (lane < 8) ? sh_s[lane] : 0.f;
        lsq  = (lane < 8) ? sh_q[lane] : 0.f;
        lsum = warpRed(lsum); lsq = warpRed(lsq);
        if (lane == 0) { g_psum[blk] = lsum; g_psq[blk] = lsq; }
    }
}

// ---------------------------------------------------------------------------
// 7x7 unbiased local variance (reflect) + gated loss partial.
// Horizontal taps straight from GMEM fp16 (2x LDG.128 per 4-output group);
// only fp32 h-sums staged in smem; one main barrier.
// ---------------------------------------------------------------------------
__global__ __launch_bounds__(256, 8) void k_localvar() {
    __shared__ float s_hs[EXTH * HSS];   // horizontal 7-sum of |rs|
    __shared__ float s_hq[EXTH * HSS];   // horizontal 7-sum of rs^2
    __shared__ float sh[8];

    int b   = blockIdx.z;
    int tx0 = blockIdx.x * TW;
    int ty0 = blockIdx.y * TH;
    int tid = threadIdx.x;

    const __half* rbh = g_rsrh + (size_t)b * HWn;

    // Phase A: horizontal 7-taps. 38 rows x 8 groups of 4 outputs.
    for (int i = tid; i < EXTH * 8; i += 256) {
        int row = i >> 3;
        int g4  = (i & 7) << 2;
        int gr  = refl(ty0 + row - 3);           // row reflect (index math only)
        const __half* rowp = rbh + gr * Wn;
        int cb = tx0 + g4 - 4;                   // window uses cols cb+1..cb+10
        float v[10];
        if (cb >= 0 && cb + 11 < Wn) {           // interior (fast path)
            int base8 = cb & ~7;                 // 16B-aligned half index
            union { uint4 u[2]; __half h[16]; } W;
            W.u[0] = *(const uint4*)(rowp + base8);
            W.u[1] = *(const uint4*)(rowp + base8 + 8);
            bool hi = (cb & 4) != 0;             // window start = base8 + 1 or + 5
            #pragma unroll
            for (int k = 0; k < 10; k++) {
                float a = __half2float(W.h[k + 1]);
                float c2 = __half2float(W.h[k + 5]);
                v[k] = fabsf(hi ? c2 : a);
            }
        } else {                                 // image border: reflect cols
            #pragma unroll
            for (int k = 0; k < 10; k++)
                v[k] = fabsf(__half2float(rowp[refl(cb + 1 + k)]));
        }
        float s0 = v[0]+v[1]+v[2]+v[3]+v[4]+v[5]+v[6];
        float s1 = s0 - v[0] + v[7];
        float s2 = s1 - v[1] + v[8];
        float s3 = s2 - v[2] + v[9];
        float q0 = v[0]*v[0]+v[1]*v[1]+v[2]*v[2]+v[3]*v[3]+v[4]*v[4]+v[5]*v[5]+v[6]*v[6];
        float q1 = q0 + (v[7]*v[7] - v[0]*v[0]);
        float q2 = q1 + (v[8]*v[8] - v[1]*v[1]);
        float q3 = q2 + (v[9]*v[9] - v[2]*v[2]);
        *(float4*)&s_hs[row * HSS + g4] = make_float4(s0, s1, s2, s3);
        *(float4*)&s_hq[row * HSS + g4] = make_float4(q0, q1, q2, q3);
    }
    __syncthreads();

    // Phase B: vertical 7-taps (register sliding window, 4 rows/thread);
    // center rs via coalesced fp16 LDG (L2-hot); gate = sign bit.
    int c  = tid & 31;
    int r0 = (tid >> 5) * 4;
    float s = 0.f, q = 0.f;
    #pragma unroll
    for (int d = 0; d < 7; d++) {
        s += s_hs[(r0 + d) * HSS + c];
        q += s_hq[(r0 + d) * HSS + c];
    }
    float acc = 0.f;
    #pragma unroll
    for (int k = 0; k < 4; k++) {
        int r = r0 + k;
        float var = (q - s * s * (1.f / 49.f)) * (1.f / 48.f);
        __half rawh = rbh[(ty0 + r) * Wn + tx0 + c];
        unsigned short u = __half_as_ushort(rawh);
        if (!(u & 0x8000u))                      // gate on (sign clear)
            acc += fabsf(var) * __half2float(rawh);
        if (k < 3) {
            s += s_hs[(r + 7) * HSS + c] - s_hs[r * HSS + c];
            q += s_hq[(r + 7) * HSS + c] - s_hq[r * HSS + c];
        }
    }

    acc = warpRed(acc);
    int lane = tid & 31, w = tid >> 5;
    if (lane == 0) sh[w] = acc;
    __syncthreads();
    if (w == 0) {
        acc = (lane < 8) ? sh[lane] : 0.f;
        acc = warpRed(acc);
        if (lane == 0)
            g_pS[(blockIdx.z * 16 + blockIdx.y) * 16 + blockIdx.x] = acc;
    }
}

// ---------------------------------------------------------------------------
// Final combine: per-image var^0.2 * S, summed. One block, 16 warps.
// ---------------------------------------------------------------------------
__global__ void k_final(float* out) {
    __shared__ double shd[16];
    int lane = threadIdx.x & 31, b = threadIdx.x >> 5;   // 512 threads
    double s = 0.0, q = 0.0, S = 0.0;
    for (int j = lane; j < 256; j += 32) {
        s += (double)g_psum[b * 256 + j];
        q += (double)g_psq [b * 256 + j];
        S += (double)g_pS  [b * 256 + j];
    }
    s = warpRedD(s); q = warpRedD(q); S = warpRedD(S);
    if (lane == 0) {
        double n   = (double)HWn;
        double var = (q - s * s / n) / (n - 1.0);
        shd[b] = pow(var, 0.2) * S;
    }
    __syncthreads();
    if (threadIdx.x == 0) {
        double tot = 0.0;
        #pragma unroll
        for (int i = 0; i < 16; i++) tot += shd[i];
        out[0] = (float)(tot / (double)((long long)Bn * 3 * HWn));
    }
}

extern "C" void kernel_launch(void* const* d_in, const int* in_sizes, int n_in,
                              void* d_out, int out_size) {
    const float* outp = (const float*)d_in[0];
    const float* emap = (const float*)d_in[1];
    const float* gtp  = (const float*)d_in[2];
    float* out = (float*)d_out;

    k_residual<<<RBLK, 256>>>(outp, emap, gtp);
    dim3 grid(Wn / TW, Hn / TH, Bn);
    k_localvar<<<grid, 256>>>();
    k_final<<<1, 512>>>(out);
}

// round 8
// speedup vs baseline: 1.1027x; 1.1027x over previous
#include <cuda_runtime.h>
#include <math.h>

#define Bn    16
#define Hn    512
#define Wn    512
#define HWn   (Hn * Wn)

// tile: 64x16 outputs, halo 3 each side
#define TW    64
#define TH    16
#define EXTH  22          // TH + 6
#define SRS   72          // s_r cols: gc tx0-4 .. tx0+67
#define HSS   68          // h-sum stride

#define NBLK  4096        // 8 x 32 x 16

__device__ float g_psum[NBLK], g_psq[NBLK], g_pS[NBLK];

__device__ __forceinline__ float warpRed(float v) {
    #pragma unroll
    for (int o = 16; o; o >>= 1) v += __shfl_down_sync(0xffffffffu, v, o);
    return v;
}
__device__ __forceinline__ double warpRedD(double v) {
    #pragma unroll
    for (int o = 16; o; o >>= 1) v += __shfl_down_sync(0xffffffffu, v, o);
    return v;
}
__device__ __forceinline__ int refl(int i) {
    i = (i < 0) ? -i : i;
    return (i >= Hn) ? (2 * (Hn - 1) - i) : i;
}

// ---------------------------------------------------------------------------
// ONE fused pass: residual + gate + per-image stats + separable 7x7 unbiased
// local variance (reflect pad) + gated loss partial. All GMEM loads float4;
// column reflection via smem mirroring (no scalar path).
// ---------------------------------------------------------------------------
__global__ __launch_bounds__(256, 6) void k_fused(const float* __restrict__ outp,
                                                  const float* __restrict__ emap,
                                                  const float* __restrict__ gtp) {
    __shared__ float  s_r [EXTH * SRS];   // rs (>=0) halo tile
    __shared__ float  s_hs[EXTH * HSS];   // horizontal 7-sum
    __shared__ float  s_hq[EXTH * HSS];   // horizontal 7-sum of squares
    __shared__ uchar4 s_g [256];          // gate bytes, 4 px each
    __shared__ float  sh  [24];

    int b   = blockIdx.z;
    int tx0 = blockIdx.x * TW;
    int ty0 = blockIdx.y * TH;
    int tid = threadIdx.x;
    int A0  = tx0 - 4;

    size_t bbase = (size_t)b * 3 * HWn;
    const float* gb = gtp  + bbase;
    const float* ob = outp + bbase;
    const float* eb = emap + bbase;

    // Phase 1: rs over halo tile, float4, row-reflect always (free).
    for (int i = tid; i < EXTH * 18; i += 256) {
        int row = i / 18, f4 = i - row * 18;
        int cb  = A0 + f4 * 4;
        if (cb >= 0 && cb <= Wn - 4) {
            int base = refl(ty0 + row - 3) * Wn + cb;
            float4 g0 = *(const float4*)(gb + base);
            float4 g1 = *(const float4*)(gb + base + HWn);
            float4 g2 = *(const float4*)(gb + base + 2 * HWn);
            float4 o0 = *(const float4*)(ob + base);
            float4 o1 = *(const float4*)(ob + base + HWn);
            float4 o2 = *(const float4*)(ob + base + 2 * HWn);
            float4 rs;
            rs.x = fabsf(g0.x-o0.x)+fabsf(g1.x-o1.x)+fabsf(g2.x-o2.x);
            rs.y = fabsf(g0.y-o0.y)+fabsf(g1.y-o1.y)+fabsf(g2.y-o2.y);
            rs.z = fabsf(g0.z-o0.z)+fabsf(g1.z-o1.z)+fabsf(g2.z-o2.z);
            rs.w = fabsf(g0.w-o0.w)+fabsf(g1.w-o1.w)+fabsf(g2.w-o2.w);
            *(float4*)&s_r[row * SRS + f4 * 4] = rs;
        }
    }
    __syncthreads();

    // Column-edge mirror fixup (left: gc -4..-1 ; right: gc 512..515).
    if (blockIdx.x == 0) {
        for (int i = tid; i < EXTH * 4; i += 256) {
            int row = i >> 2, k = i & 3;
            s_r[row * SRS + k] = s_r[row * SRS + 8 - k];
        }
    } else if (blockIdx.x == (Wn / TW) - 1) {
        for (int i = tid; i < EXTH * 4; i += 256) {
            int row = i >> 2, k = i & 3;
            s_r[row * SRS + 68 + k] = s_r[row * SRS + 66 - k];
        }
    }

    // Gate + per-image stats on center pixels (gt/out L1-hot, ema fresh).
    float lsum, lsq;
    {
        int r  = tid >> 4;
        int c4 = (tid & 15) * 4;
        int base = (ty0 + r) * Wn + tx0 + c4;
        float4 g0 = *(const float4*)(gb + base);
        float4 g1 = *(const float4*)(gb + base + HWn);
        float4 g2 = *(const float4*)(gb + base + 2 * HWn);
        float4 e0 = *(const float4*)(eb + base);
        float4 e1 = *(const float4*)(eb + base + HWn);
        float4 e2 = *(const float4*)(eb + base + 2 * HWn);
        float4 rs = *(const float4*)&s_r[(r + 3) * SRS + c4 + 4];
        float4 re;
        re.x = fabsf(g0.x-e0.x)+fabsf(g1.x-e1.x)+fabsf(g2.x-e2.x);
        re.y = fabsf(g0.y-e0.y)+fabsf(g1.y-e1.y)+fabsf(g2.y-e2.y);
        re.z = fabsf(g0.z-e0.z)+fabsf(g1.z-e1.z)+fabsf(g2.z-e2.z);
        re.w = fabsf(g0.w-e0.w)+fabsf(g1.w-e1.w)+fabsf(g2.w-e2.w);
        uchar4 gv;
        gv.x = (rs.x < re.x) ? 0 : 1;
        gv.y = (rs.y < re.y) ? 0 : 1;
        gv.z = (rs.z < re.z) ? 0 : 1;
        gv.w = (rs.w < re.w) ? 0 : 1;
        s_g[tid] = gv;
        lsum = rs.x + rs.y + rs.z + rs.w;
        lsq  = rs.x*rs.x + rs.y*rs.y + rs.z*rs.z + rs.w*rs.w;
    }
    __syncthreads();

    // Phase 2: horizontal 7-taps, 4 outputs/thread, sliding window.
    for (int i = tid; i < EXTH * 16; i += 256) {
        int row = i >> 4;
        int g4  = (i & 15) << 2;
        const float* rp = &s_r[row * SRS + g4];
        float4 A  = *(const float4*)(rp);
        float4 Bv = *(const float4*)(rp + 4);
        float4 Cv = *(const float4*)(rp + 8);
        float v0=A.y, v1=A.z, v2=A.w, v3=Bv.x, v4=Bv.y, v5=Bv.z, v6=Bv.w;
        float v7=Cv.x, v8=Cv.y, v9=Cv.z;
        float s0 = v0+v1+v2+v3+v4+v5+v6;
        float s1 = s0 - v0 + v7;
        float s2 = s1 - v1 + v8;
        float s3 = s2 - v2 + v9;
        float q0 = v0*v0+v1*v1+v2*v2+v3*v3+v4*v4+v5*v5+v6*v6;
        float q1 = q0 + (v7*v7 - v0*v0);
        float q2 = q1 + (v8*v8 - v1*v1);
        float q3 = q2 + (v9*v9 - v2*v2);
        *(float4*)&s_hs[row * HSS + g4] = make_float4(s0, s1, s2, s3);
        *(float4*)&s_hq[row * HSS + g4] = make_float4(q0, q1, q2, q3);
    }
    __syncthreads();

    // Phase 3: vertical 7-taps, register sliding window, 4 rows/thread.
    int c  = tid & 63;
    int r0 = (tid >> 6) * 4;
    float s = 0.f, q = 0.f;
    #pragma unroll
    for (int d = 0; d < 7; d++) {
        s += s_hs[(r0 + d) * HSS + c];
        q += s_hq[(r0 + d) * HSS + c];
    }
    float acc = 0.f;
    #pragma unroll
    for (int k = 0; k < 4; k++) {
        int r = r0 + k;
        float var = (q - s * s * (1.f / 49.f)) * (1.f / 48.f);
        float rs  = s_r[(r + 3) * SRS + c + 4];
        uchar4 gv = s_g[r * 16 + (c >> 2)];
        unsigned char gbit = (c & 2) ? ((c & 1) ? gv.w : gv.z)
                                     : ((c & 1) ? gv.y : gv.x);
        if (gbit) acc += fabsf(var) * rs;
        if (k < 3) {
            s += s_hs[(r + 7) * HSS + c] - s_hs[r * HSS + c];
            q += s_hq[(r + 7) * HSS + c] - s_hq[r * HSS + c];
        }
    }

    // Block reduce (lsum, lsq, acc) -> per-block partials.
    float a0 = warpRed(lsum), a1 = warpRed(lsq), a2 = warpRed(acc);
    int lane = tid & 31, w = tid >> 5;
    if (lane == 0) { sh[w] = a0; sh[8 + w] = a1; sh[16 + w] = a2; }
    __syncthreads();
    if (w == 0) {
        a0 = (lane < 8) ? sh[lane]      : 0.f;
        a1 = (lane < 8) ? sh[8 + lane]  : 0.f;
        a2 = (lane < 8) ? sh[16 + lane] : 0.f;
        a0 = warpRed(a0); a1 = warpRed(a1); a2 = warpRed(a2);
        if (lane == 0) {
            int blk = (blockIdx.z * 32 + blockIdx.y) * 8 + blockIdx.x;
            g_psum[blk] = a0; g_psq[blk] = a1; g_pS[blk] = a2;
        }
    }
}

// ---------------------------------------------------------------------------
// Final combine: per-image var^0.2 * S, summed. One block, 16 warps.
// ---------------------------------------------------------------------------
__global__ void k_final(float* out) {
    __shared__ double shd[16];
    int lane = threadIdx.x & 31, b = threadIdx.x >> 5;   // 512 threads
    double s = 0.0, q = 0.0, S = 0.0;
    for (int j = lane; j < 256; j += 32) {
        s += (double)g_psum[b * 256 + j];
        q += (double)g_psq [b * 256 + j];
        S += (double)g_pS  [b * 256 + j];
    }
    s = warpRedD(s); q = warpRedD(q); S = warpRedD(S);
    if (lane == 0) {
        double n   = (double)HWn;
        double var = (q - s * s / n) / (n - 1.0);
        shd[b] = pow(var, 0.2) * S;
    }
    __syncthreads();
    if (threadIdx.x == 0) {
        double tot = 0.0;
        #pragma unroll
        for (int i = 0; i < 16; i++) tot += shd[i];
        out[0] = (float)(tot / (double)((long long)Bn * 3 * HWn));
    }
}

extern "C" void kernel_launch(void* const* d_in, const int* in_sizes, int n_in,
                              void* d_out, int out_size) {
    const float* outp = (const float*)d_in[0];
    const float* emap = (const float*)d_in[1];
    const float* gtp  = (const float*)d_in[2];
    float* out = (float*)d_out;

    dim3 grid(Wn / TW, Hn / TH, Bn);
    k_fused<<<grid, 256>>>(outp, emap, gtp);
    k_final<<<1, 512>>>(out);
}

// round 9
// speedup vs baseline: 1.3869x; 1.2577x over previous
#include <cuda_runtime.h>
#include <math.h>

#define Bn    16
#define Hn    512
#define Wn    512
#define HWn   (Hn * Wn)

// tile: 64x16 outputs, halo 3 each side
#define TW    64
#define TH    16
#define EXTH  22          // TH + 6
#define SRS   72          // s_r cols: gc tx0-4 .. tx0+67
#define HSS   68          // h-sum stride

#define NBLK  4096        // 8 x 32 x 16

__device__ float g_psum[NBLK], g_psq[NBLK], g_pS[NBLK];

__device__ __forceinline__ float warpRed(float v) {
    #pragma unroll
    for (int o = 16; o; o >>= 1) v += __shfl_down_sync(0xffffffffu, v, o);
    return v;
}
__device__ __forceinline__ double warpRedD(double v) {
    #pragma unroll
    for (int o = 16; o; o >>= 1) v += __shfl_down_sync(0xffffffffu, v, o);
    return v;
}
__device__ __forceinline__ int refl(int i) {
    i = (i < 0) ? -i : i;
    return (i >= Hn) ? (2 * (Hn - 1) - i) : i;
}

// ---------------------------------------------------------------------------
// ONE fused pass: residual + gate + per-image stats + separable 7x7 unbiased
// local variance (reflect pad) + gated loss partial. All GMEM loads float4;
// column reflection via smem mirroring (no scalar path).
// ---------------------------------------------------------------------------
__global__ __launch_bounds__(256, 6) void k_fused(const float* __restrict__ outp,
                                                  const float* __restrict__ emap,
                                                  const float* __restrict__ gtp) {
    __shared__ float  s_r [EXTH * SRS];   // rs (>=0) halo tile
    __shared__ float  s_hs[EXTH * HSS];   // horizontal 7-sum
    __shared__ float  s_hq[EXTH * HSS];   // horizontal 7-sum of squares
    __shared__ uchar4 s_g [256];          // gate bytes, 4 px each
    __shared__ float  sh  [24];

    int b   = blockIdx.z;
    int tx0 = blockIdx.x * TW;
    int ty0 = blockIdx.y * TH;
    int tid = threadIdx.x;
    int A0  = tx0 - 4;

    size_t bbase = (size_t)b * 3 * HWn;
    const float* gb = gtp  + bbase;
    const float* ob = outp + bbase;
    const float* eb = emap + bbase;

    // Phase 1: rs over halo tile, float4, row-reflect always (free).
    for (int i = tid; i < EXTH * 18; i += 256) {
        int row = i / 18, f4 = i - row * 18;
        int cb  = A0 + f4 * 4;
        if (cb >= 0 && cb <= Wn - 4) {
            int base = refl(ty0 + row - 3) * Wn + cb;
            float4 g0 = *(const float4*)(gb + base);
            float4 g1 = *(const float4*)(gb + base + HWn);
            float4 g2 = *(const float4*)(gb + base + 2 * HWn);
            float4 o0 = *(const float4*)(ob + base);
            float4 o1 = *(const float4*)(ob + base + HWn);
            float4 o2 = *(const float4*)(ob + base + 2 * HWn);
            float4 rs;
            rs.x = fabsf(g0.x-o0.x)+fabsf(g1.x-o1.x)+fabsf(g2.x-o2.x);
            rs.y = fabsf(g0.y-o0.y)+fabsf(g1.y-o1.y)+fabsf(g2.y-o2.y);
            rs.z = fabsf(g0.z-o0.z)+fabsf(g1.z-o1.z)+fabsf(g2.z-o2.z);
            rs.w = fabsf(g0.w-o0.w)+fabsf(g1.w-o1.w)+fabsf(g2.w-o2.w);
            *(float4*)&s_r[row * SRS + f4 * 4] = rs;
        }
    }
    __syncthreads();

    // Column-edge mirror fixup (left: gc -4..-1 ; right: gc 512..515).
    if (blockIdx.x == 0) {
        for (int i = tid; i < EXTH * 4; i += 256) {
            int row = i >> 2, k = i & 3;
            s_r[row * SRS + k] = s_r[row * SRS + 8 - k];
        }
    } else if (blockIdx.x == (Wn / TW) - 1) {
        for (int i = tid; i < EXTH * 4; i += 256) {
            int row = i >> 2, k = i & 3;
            s_r[row * SRS + 68 + k] = s_r[row * SRS + 66 - k];
        }
    }

    // Gate + per-image stats on center pixels (gt/out L1-hot, ema fresh).
    float lsum, lsq;
    {
        int r  = tid >> 4;
        int c4 = (tid & 15) * 4;
        int base = (ty0 + r) * Wn + tx0 + c4;
        float4 g0 = *(const float4*)(gb + base);
        float4 g1 = *(const float4*)(gb + base + HWn);
        float4 g2 = *(const float4*)(gb + base + 2 * HWn);
        float4 e0 = *(const float4*)(eb + base);
        float4 e1 = *(const float4*)(eb + base + HWn);
        float4 e2 = *(const float4*)(eb + base + 2 * HWn);
        float4 rs = *(const float4*)&s_r[(r + 3) * SRS + c4 + 4];
        float4 re;
        re.x = fabsf(g0.x-e0.x)+fabsf(g1.x-e1.x)+fabsf(g2.x-e2.x);
        re.y = fabsf(g0.y-e0.y)+fabsf(g1.y-e1.y)+fabsf(g2.y-e2.y);
        re.z = fabsf(g0.z-e0.z)+fabsf(g1.z-e1.z)+fabsf(g2.z-e2.z);
        re.w = fabsf(g0.w-e0.w)+fabsf(g1.w-e1.w)+fabsf(g2.w-e2.w);
        uchar4 gv;
        gv.x = (rs.x < re.x) ? 0 : 1;
        gv.y = (rs.y < re.y) ? 0 : 1;
        gv.z = (rs.z < re.z) ? 0 : 1;
        gv.w = (rs.w < re.w) ? 0 : 1;
        s_g[tid] = gv;
        lsum = rs.x + rs.y + rs.z + rs.w;
        lsq  = rs.x*rs.x + rs.y*rs.y + rs.z*rs.z + rs.w*rs.w;
    }
    __syncthreads();

    // Phase 2: horizontal 7-taps, 4 outputs/thread, sliding window.
    for (int i = tid; i < EXTH * 16; i += 256) {
        int row = i >> 4;
        int g4  = (i & 15) << 2;
        const float* rp = &s_r[row * SRS + g4];
        float4 A  = *(const float4*)(rp);
        float4 Bv = *(const float4*)(rp + 4);
        float4 Cv = *(const float4*)(rp + 8);
        float v0=A.y, v1=A.z, v2=A.w, v3=Bv.x, v4=Bv.y, v5=Bv.z, v6=Bv.w;
        float v7=Cv.x, v8=Cv.y, v9=Cv.z;
        float s0 = v0+v1+v2+v3+v4+v5+v6;
        float s1 = s0 - v0 + v7;
        float s2 = s1 - v1 + v8;
        float s3 = s2 - v2 + v9;
        float q0 = v0*v0+v1*v1+v2*v2+v3*v3+v4*v4+v5*v5+v6*v6;
        float q1 = q0 + (v7*v7 - v0*v0);
        float q2 = q1 + (v8*v8 - v1*v1);
        float q3 = q2 + (v9*v9 - v2*v2);
        *(float4*)&s_hs[row * HSS + g4] = make_float4(s0, s1, s2, s3);
        *(float4*)&s_hq[row * HSS + g4] = make_float4(q0, q1, q2, q3);
    }
    __syncthreads();

    // Phase 3: vertical 7-taps, register sliding window, 4 rows/thread.
    int c  = tid & 63;
    int r0 = (tid >> 6) * 4;
    float s = 0.f, q = 0.f;
    #pragma unroll
    for (int d = 0; d < 7; d++) {
        s += s_hs[(r0 + d) * HSS + c];
        q += s_hq[(r0 + d) * HSS + c];
    }
    float acc = 0.f;
    #pragma unroll
    for (int k = 0; k < 4; k++) {
        int r = r0 + k;
        float var = (q - s * s * (1.f / 49.f)) * (1.f / 48.f);
        float rs  = s_r[(r + 3) * SRS + c + 4];
        uchar4 gv = s_g[r * 16 + (c >> 2)];
        unsigned char gbit = (c & 2) ? ((c & 1) ? gv.w : gv.z)
                                     : ((c & 1) ? gv.y : gv.x);
        if (gbit) acc += fabsf(var) * rs;
        if (k < 3) {
            s += s_hs[(r + 7) * HSS + c] - s_hs[r * HSS + c];
            q += s_hq[(r + 7) * HSS + c] - s_hq[r * HSS + c];
        }
    }

    // Block reduce (lsum, lsq, acc) -> per-block partials.
    float a0 = warpRed(lsum), a1 = warpRed(lsq), a2 = warpRed(acc);
    int lane = tid & 31, w = tid >> 5;
    if (lane == 0) { sh[w] = a0; sh[8 + w] = a1; sh[16 + w] = a2; }
    __syncthreads();
    if (w == 0) {
        a0 = (lane < 8) ? sh[lane]      : 0.f;
        a1 = (lane < 8) ? sh[8 + lane]  : 0.f;
        a2 = (lane < 8) ? sh[16 + lane] : 0.f;
        a0 = warpRed(a0); a1 = warpRed(a1); a2 = warpRed(a2);
        if (lane == 0) {
            int blk = (blockIdx.z * 32 + blockIdx.y) * 8 + blockIdx.x;
            g_psum[blk] = a0; g_psq[blk] = a1; g_pS[blk] = a2;
        }
    }
}

// ---------------------------------------------------------------------------
// Final combine. Double only for the sums (cancellation); powf for the ^0.2
// (FP64 pow was the R8 bottleneck: ~28us of serial DP chain on 16 lanes).
// ---------------------------------------------------------------------------
__global__ void k_final(float* out) {
    __shared__ double shd[16];
    int lane = threadIdx.x & 31, b = threadIdx.x >> 5;   // 512 threads, 16 warps
    double s = 0.0, q = 0.0, S = 0.0;
    #pragma unroll
    for (int j = 0; j < 8; j++) {
        int idx = b * 256 + j * 32 + lane;
        s += (double)g_psum[idx];
        q += (double)g_psq [idx];
        S += (double)g_pS  [idx];
    }
    s = warpRedD(s); q = warpRedD(q); S = warpRedD(S);
    if (lane == 0) {
        double n   = (double)HWn;
        double var = (q - s * s / n) / (n - 1.0);
        shd[b] = (double)powf((float)var, 0.2f) * S;
    }
    __syncthreads();
    if (threadIdx.x == 0) {
        double tot = 0.0;
        #pragma unroll
        for (int i = 0; i < 16; i++) tot += shd[i];
        out[0] = (float)(tot / (double)((long long)Bn * 3 * HWn));
    }
}

extern "C" void kernel_launch(void* const* d_in, const int* in_sizes, int n_in,
                              void* d_out, int out_size) {
    const float* outp = (const float*)d_in[0];
    const float* emap = (const float*)d_in[1];
    const float* gtp  = (const float*)d_in[2];
    float* out = (float*)d_out;

    dim3 grid(Wn / TW, Hn / TH, Bn);
    k_fused<<<grid, 256>>>(outp, emap, gtp);
    k_final<<<1, 512>>>(out);
}